// round 7
// baseline (speedup 1.0000x reference)
#include <cuda_runtime.h>
#include <math.h>

#define HH 512
#define WW 512
#define BB 2
#define HWSZ (HH*WW)
#define NPIX (BB*HWSZ)
#define TOPK 2048
#define CAP 262144
#define NKP (BB*TOPK)
#define NBINS 4096

#define KXY_OFF  0
#define DESC_OFF (BB*TOPK*2)
#define SC_OFF   (DESC_OFF + BB*TOPK*128)
#define DISP_OFF (SC_OFF + BB*TOPK)

#define CTX 64
#define CTY 32
#define HAL 15
#define BW  96
#define BHT 62
#define NBUF (BHT*BW)

__device__ unsigned long long g_cand[BB*CAP];
__device__ unsigned long long g_surv[BB*CAP];
__device__ int g_count[BB];
__device__ int g_scount[BB];
__device__ int g_T[BB];
__device__ int g_hist[BB*NBINS];
__device__ int g_selidx[NKP];

// Fully-fused split-half NMS (5 pools + mask logic + compaction + histogram).
__global__ __launch_bounds__(512) void nms_k(const float* __restrict__ scores) {
    extern __shared__ float sh[];
    float* S  = sh;
    float* MM = sh + NBUF;
    float* SS = sh + 2*NBUF;
    float* TP = sh + 3*NBUF;

    int tid = threadIdx.x;
    int b   = blockIdx.z;
    int gx0 = blockIdx.x * CTX - HAL;
    int gy0 = blockIdx.y * CTY - HAL;
    int hlo = ((int)(blockIdx.y * CTY) < 256) ? 0 : 256;
    int hhi = hlo + 255;
    const float* sb = scores + b * HWSZ;

    for (int idx = tid; idx < NBUF; idx += 512) {
        int br = idx / BW, bc = idx % BW;
        int gy = gy0 + br, gx = gx0 + bc;
        float v = -INFINITY;
        if (bc < 94 && gy >= hlo && gy <= hhi && gx >= 0 && gx < WW)
            v = sb[gy * WW + gx];
        S[idx] = v;
    }
    __syncthreads();

#define VPASS(SRC, H)                                                          \
    {                                                                          \
        const int R = CTY + 2*(H), C = CTX + 2*(H) + 6;                        \
        for (int idx = tid; idx < R*C; idx += 512) {                           \
            int o = ((HAL-(H)) + idx / C) * BW + ((HAL-(H)-3) + idx % C);      \
            float m =        SRC[o - 3*BW];                                    \
            m = fmaxf(m, SRC[o - 2*BW]); m = fmaxf(m, SRC[o - BW]);            \
            m = fmaxf(m, SRC[o]);        m = fmaxf(m, SRC[o + BW]);            \
            m = fmaxf(m, SRC[o + 2*BW]); m = fmaxf(m, SRC[o + 3*BW]);          \
            TP[o] = m;                                                         \
        }                                                                      \
        __syncthreads();                                                       \
    }

#define HMAX(o, m)                                                             \
    float m =        TP[(o) - 3];                                              \
    m = fmaxf(m, TP[(o) - 2]); m = fmaxf(m, TP[(o) - 1]);                      \
    m = fmaxf(m, TP[(o)]);     m = fmaxf(m, TP[(o) + 1]);                      \
    m = fmaxf(m, TP[(o) + 2]); m = fmaxf(m, TP[(o) + 3]);

    // stage 1 (out halo 12): mm = (s == pool(s)); invalid -> -inf
    VPASS(S, 12)
    {
        const int R = CTY + 24, C = CTX + 24;
        for (int idx = tid; idx < R*C; idx += 512) {
            int br = 3 + idx / C, bc = 3 + idx % C;
            int o = br * BW + bc;
            HMAX(o, m)
            int gy = gy0 + br, gx = gx0 + bc;
            bool valid = gy >= hlo && gy <= hhi && gx >= 0 && gx < WW;
            MM[o] = valid ? ((S[o] == m) ? 1.0f : 0.0f) : -INFINITY;
        }
        __syncthreads();
    }

    // iteration 1
    VPASS(MM, 9)
    {
        const int R = CTY + 18, C = CTX + 18;
        for (int idx = tid; idx < R*C; idx += 512) {
            int br = 6 + idx / C, bc = 6 + idx % C;
            int o = br * BW + bc;
            HMAX(o, m)
            int gy = gy0 + br, gx = gx0 + bc;
            bool valid = gy >= hlo && gy <= hhi && gx >= 0 && gx < WW;
            SS[o] = valid ? ((m > 0.0f) ? -1.0f : S[o]) : -INFINITY;
        }
        __syncthreads();
    }
    VPASS(SS, 6)
    {
        const int R = CTY + 12, C = CTX + 12;
        for (int idx = tid; idx < R*C; idx += 512) {
            int br = 9 + idx / C, bc = 9 + idx % C;
            int o = br * BW + bc;
            HMAX(o, m)
            float ssv = SS[o];
            if (MM[o] == 0.0f && ssv >= 0.0f && ssv == m) MM[o] = 1.0f;
        }
        __syncthreads();
    }

    // iteration 2 + fused compaction
    VPASS(MM, 3)
    {
        const int R = CTY + 6, C = CTX + 6;
        for (int idx = tid; idx < R*C; idx += 512) {
            int br = 12 + idx / C, bc = 12 + idx % C;
            int o = br * BW + bc;
            HMAX(o, m)
            int gy = gy0 + br, gx = gx0 + bc;
            bool valid = gy >= hlo && gy <= hhi && gx >= 0 && gx < WW;
            SS[o] = valid ? ((m > 0.0f) ? -1.0f : S[o]) : -INFINITY;
        }
        __syncthreads();
    }
    VPASS(SS, 0)
    {
        for (int idx = tid; idx < CTY*CTX; idx += 512) {
            int br = HAL + idx / CTX, bc = HAL + idx % CTX;
            int o = br * BW + bc;
            HMAX(o, m)
            float ssv = SS[o];
            float mmv = MM[o];
            if (mmv == 0.0f && ssv >= 0.0f && ssv == m) mmv = 1.0f;
            int gy = gy0 + br, gx = gx0 + bc;
            int rem = gy * WW + gx;
            bool border = (gy >= 3) && (gy < 510) && (gx >= 3) && (gx < 510);
            float nms = (mmv > 0.0f && border) ? S[o] : 0.0f;
            if (nms > 0.0f || rem < TOPK) {
                int pos = atomicAdd(&g_count[b], 1);
                if (pos < CAP) {
                    unsigned long long key =
                        ((unsigned long long)__float_as_uint(nms) << 32) |
                        (unsigned long long)(0xFFFFFFFFu - (unsigned)rem);
                    g_cand[b * CAP + pos] = key;
                    int bin = min(NBINS-1, max(0, (int)(nms * (float)NBINS)));
                    atomicAdd(&g_hist[b * NBINS + bin], 1);
                }
            }
        }
    }
}

// per-batch: find smallest bin T with suffix-count >= TOPK; then zero hist
__global__ __launch_bounds__(1024) void thresh_k() {
    int b = blockIdx.x;
    int t = threadIdx.x;
    __shared__ int gs[1024];
    int base = NBINS - 1 - 4*t;
    int c0 = g_hist[b*NBINS + base];
    int c1 = g_hist[b*NBINS + base-1];
    int c2 = g_hist[b*NBINS + base-2];
    int c3 = g_hist[b*NBINS + base-3];
    int s = c0 + c1 + c2 + c3;
    gs[t] = s;
    __syncthreads();
    for (int off = 1; off < 1024; off <<= 1) {
        int v = (t >= off) ? gs[t-off] : 0;
        __syncthreads();
        gs[t] += v;
        __syncthreads();
    }
    int total = gs[1023];
    int excl = gs[t] - s;
    if (excl < TOPK && excl + s >= TOPK) {
        int T = base - 3;
        int cum = excl + c0;
        if (cum >= TOPK) T = base;
        else { cum += c1; if (cum >= TOPK) T = base-1;
               else { cum += c2; if (cum >= TOPK) T = base-2; } }
        g_T[b] = T;
    }
    if (t == 0 && total < TOPK) g_T[b] = 0;
    // reset histogram for next graph replay (after all reads above)
    g_hist[b*NBINS + base]   = 0;
    g_hist[b*NBINS + base-1] = 0;
    g_hist[b*NBINS + base-2] = 0;
    g_hist[b*NBINS + base-3] = 0;
}

#define CBLK 32

// keep only candidates with bin >= T (small grid + stride)
__global__ __launch_bounds__(256) void compact2_k() {
    int b = blockIdx.y;
    int cnt = min(g_count[b], CAP);
    int T = g_T[b];
    for (int i = blockIdx.x * 256 + threadIdx.x; i < cnt; i += CBLK * 256) {
        unsigned long long key = g_cand[b*CAP + i];
        float v = __uint_as_float((unsigned)(key >> 32));
        int bin = min(NBINS-1, max(0, (int)(v * (float)NBINS)));
        if (bin >= T) {
            int p = atomicAdd(&g_scount[b], 1);
            g_surv[b*CAP + p] = key;
        }
    }
}

// exact rank among survivors; also resets g_count for next replay
__global__ __launch_bounds__(256) void rank2_k() {
    int b = blockIdx.y;
    int m = g_scount[b];
    const unsigned long long* sv = g_surv + b*CAP;
    __shared__ unsigned long long sk[256];
    for (int i0 = blockIdx.x * 256; i0 < m; i0 += CBLK * 256) {
        int i = i0 + threadIdx.x;
        unsigned long long mykey = (i < m) ? sv[i] : 0ull;
        int rank = 0;
        for (int t = 0; t < m; t += 256) {
            int j = t + threadIdx.x;
            sk[threadIdx.x] = (j < m) ? sv[j] : 0ull;
            __syncthreads();
            int lim = min(256, m - t);
            if (i < m) {
                int u = 0;
                for (; u + 4 <= lim; u += 4) {
                    rank += (sk[u]   > mykey) ? 1 : 0;
                    rank += (sk[u+1] > mykey) ? 1 : 0;
                    rank += (sk[u+2] > mykey) ? 1 : 0;
                    rank += (sk[u+3] > mykey) ? 1 : 0;
                }
                for (; u < lim; ++u) rank += (sk[u] > mykey) ? 1 : 0;
            }
            __syncthreads();
        }
        if (i < m && rank < TOPK) {
            int flatidx = (int)(0xFFFFFFFFu - (unsigned)(mykey & 0xFFFFFFFFull));
            g_selidx[b * TOPK + rank] = flatidx;
        }
    }
    // rank2 never reads g_count; safe to reset here for next replay
    if (blockIdx.x == 0 && threadIdx.x == 0) g_count[b] = 0;
}

__device__ __forceinline__ float bilin1(const float* base, float x, float y) {
    float x0f = floorf(x), y0f = floorf(y);
    float wx = x - x0f, wy = y - y0f;
    int x0 = min(max((int)x0f, 0), WW - 1);
    int x1 = min(max((int)x0f + 1, 0), WW - 1);
    int y0 = min(max((int)y0f, 0), HH - 1);
    int y1 = min(max((int)y0f + 1, 0), HH - 1);
    float v00 = base[y0 * WW + x0], v01 = base[y0 * WW + x1];
    float v10 = base[y1 * WW + x0], v11 = base[y1 * WW + x1];
    return v00 * (1.f - wx) * (1.f - wy) + v01 * wx * (1.f - wy)
         + v10 * (1.f - wx) * wy + v11 * wx * wy;
}

// fused: warp0 does 5x5 softmax refine; all 128 threads sample+normalize desc
__global__ __launch_bounds__(128) void refine_desc_k(const float* __restrict__ scores,
                                                     const float* __restrict__ dmap,
                                                     float* __restrict__ out) {
    int t = blockIdx.x;
    int c = threadIdx.x;
    int b = t >> 11;
    int w = c >> 5, lane = c & 31;
    __shared__ float sxy[2];

    if (t == 0 && c < BB) g_scount[c] = 0;   // reset for next replay

    if (w == 0) {
        int idx = g_selidx[t];
        int ky = idx >> 9, kx = idx & 511;
        const float* sb = scores + b * HWSZ;
        int p = lane;
        float dxf = 0.f, dyf = 0.f, v = 0.f;
        if (p < 25) {
            int dy = p / 5 - 2, dx = p % 5 - 2;
            dxf = (float)dx; dyf = (float)dy;
            int y = ky + dy, x = kx + dx;
            v = (y >= 0 && y < HH && x >= 0 && x < WW) ? sb[y * WW + x] : 0.0f;
        }
        float pv = (p < 25) ? v : -INFINITY;
#pragma unroll
        for (int o = 16; o > 0; o >>= 1) pv = fmaxf(pv, __shfl_xor_sync(0xFFFFFFFFu, pv, o));
        float e = (p < 25) ? expf((v - pv) * 10.0f) : 0.0f;
        float se = e, sxv = e * dxf, syv = e * dyf;
#pragma unroll
        for (int o = 16; o > 0; o >>= 1) {
            se  += __shfl_xor_sync(0xFFFFFFFFu, se, o);
            sxv += __shfl_xor_sync(0xFFFFFFFFu, sxv, o);
            syv += __shfl_xor_sync(0xFFFFFFFFu, syv, o);
        }
        float rx = sxv / se, ry = syv / se;
        float ddx = (dxf - rx) * 0.5f, ddy = (dyf - ry) * 0.5f;
        float dc = e * (ddx * ddx + ddy * ddy);
#pragma unroll
        for (int o = 16; o > 0; o >>= 1) dc += __shfl_xor_sync(0xFFFFFFFFu, dc, o);

        if (lane == 0) {
            float kxf = ((float)kx + rx) / 511.f * 2.f - 1.f;
            float kyf = ((float)ky + ry) / 511.f * 2.f - 1.f;
            out[KXY_OFF + t * 2 + 0] = kxf;
            out[KXY_OFF + t * 2 + 1] = kyf;
            out[DISP_OFF + t] = dc / se;
            float xs = (kxf + 1.f) * 0.5f * (WW - 1);
            float ys = (kyf + 1.f) * 0.5f * (HH - 1);
            out[SC_OFF + t] = bilin1(sb, xs, ys);
            sxy[0] = xs; sxy[1] = ys;
        }
    }
    __syncthreads();

    float x = sxy[0], y = sxy[1];
    float x0f = floorf(x), y0f = floorf(y);
    float wx = x - x0f, wy = y - y0f;
    int x0 = min(max((int)x0f, 0), WW - 1);
    int x1 = min(max((int)x0f + 1, 0), WW - 1);
    int y0 = min(max((int)y0f, 0), HH - 1);
    int y1 = min(max((int)y0f + 1, 0), HH - 1);
    const float* base = dmap + ((size_t)b * 128 + c) * HWSZ;
    float v00 = base[y0 * WW + x0], v01 = base[y0 * WW + x1];
    float v10 = base[y1 * WW + x0], v11 = base[y1 * WW + x1];
    float v = v00 * (1.f - wx) * (1.f - wy) + v01 * wx * (1.f - wy)
            + v10 * (1.f - wx) * wy + v11 * wx * wy;

    float sq = v * v;
#pragma unroll
    for (int o = 16; o > 0; o >>= 1) sq += __shfl_xor_sync(0xFFFFFFFFu, sq, o);
    __shared__ float wsum[4];
    if (lane == 0) wsum[w] = sq;
    __syncthreads();
    float tot = wsum[0] + wsum[1] + wsum[2] + wsum[3];
    float nrm = fmaxf(sqrtf(tot), 1e-12f);
    out[DESC_OFF + (size_t)t * 128 + c] = v / nrm;
}

extern "C" void kernel_launch(void* const* d_in, const int* in_sizes, int n_in,
                              void* d_out, int out_size) {
    const float* scores;
    const float* dmap;
    if (in_sizes[0] == NPIX) {
        scores = (const float*)d_in[0];
        dmap   = (const float*)d_in[1];
    } else {
        scores = (const float*)d_in[1];
        dmap   = (const float*)d_in[0];
    }
    float* out = (float*)d_out;

    static bool attr_done = false;
    if (!attr_done) {
        cudaFuncSetAttribute(nms_k, cudaFuncAttributeMaxDynamicSharedMemorySize,
                             4 * NBUF * (int)sizeof(float));
        attr_done = true;
    }

    dim3 ng(WW / CTX, HH / CTY, BB);
    nms_k<<<ng, 512, 4 * NBUF * sizeof(float)>>>(scores);

    thresh_k<<<BB, 1024>>>();

    dim3 cg(CBLK, BB);
    compact2_k<<<cg, 256>>>();
    rank2_k<<<cg, 256>>>();

    refine_desc_k<<<NKP, 128>>>(scores, dmap, out);
}

// round 8
// speedup vs baseline: 1.0306x; 1.0306x over previous
#include <cuda_runtime.h>
#include <math.h>

#define HH 512
#define WW 512
#define BB 2
#define HWSZ (HH*WW)
#define NPIX (BB*HWSZ)
#define TOPK 2048
#define CAP 262144
#define NKP (BB*TOPK)
#define NBINS 4096
#define MAXS 32768

#define KXY_OFF  0
#define DESC_OFF (BB*TOPK*2)
#define SC_OFF   (DESC_OFF + BB*TOPK*128)
#define DISP_OFF (SC_OFF + BB*TOPK)

#define CTX 64
#define CTY 32
#define HAL 15
#define BW  96
#define BHT 62
#define NBUF (BHT*BW)

__device__ unsigned long long g_cand[BB*CAP];
__device__ unsigned long long g_surv[BB*MAXS];
__device__ int g_count[BB];
__device__ int g_scount[BB];
__device__ int g_hist[BB*NBINS];
__device__ int g_rank[BB*MAXS];
__device__ int g_selidx[NKP];

// Fully-fused split-half NMS (5 pools + mask logic + compaction + histogram).
__global__ __launch_bounds__(512) void nms_k(const float* __restrict__ scores) {
    extern __shared__ float sh[];
    float* S  = sh;
    float* MM = sh + NBUF;
    float* SS = sh + 2*NBUF;
    float* TP = sh + 3*NBUF;

    int tid = threadIdx.x;
    int b   = blockIdx.z;
    int gx0 = blockIdx.x * CTX - HAL;
    int gy0 = blockIdx.y * CTY - HAL;
    int hlo = ((int)(blockIdx.y * CTY) < 256) ? 0 : 256;
    int hhi = hlo + 255;
    const float* sb = scores + b * HWSZ;

    for (int idx = tid; idx < NBUF; idx += 512) {
        int br = idx / BW, bc = idx % BW;
        int gy = gy0 + br, gx = gx0 + bc;
        float v = -INFINITY;
        if (bc < 94 && gy >= hlo && gy <= hhi && gx >= 0 && gx < WW)
            v = sb[gy * WW + gx];
        S[idx] = v;
    }
    __syncthreads();

#define VPASS(SRC, H)                                                          \
    {                                                                          \
        const int R = CTY + 2*(H), C = CTX + 2*(H) + 6;                        \
        for (int idx = tid; idx < R*C; idx += 512) {                           \
            int o = ((HAL-(H)) + idx / C) * BW + ((HAL-(H)-3) + idx % C);      \
            float m =        SRC[o - 3*BW];                                    \
            m = fmaxf(m, SRC[o - 2*BW]); m = fmaxf(m, SRC[o - BW]);            \
            m = fmaxf(m, SRC[o]);        m = fmaxf(m, SRC[o + BW]);            \
            m = fmaxf(m, SRC[o + 2*BW]); m = fmaxf(m, SRC[o + 3*BW]);          \
            TP[o] = m;                                                         \
        }                                                                      \
        __syncthreads();                                                       \
    }

#define HMAX(o, m)                                                             \
    float m =        TP[(o) - 3];                                              \
    m = fmaxf(m, TP[(o) - 2]); m = fmaxf(m, TP[(o) - 1]);                      \
    m = fmaxf(m, TP[(o)]);     m = fmaxf(m, TP[(o) + 1]);                      \
    m = fmaxf(m, TP[(o) + 2]); m = fmaxf(m, TP[(o) + 3]);

    // stage 1 (out halo 12): mm = (s == pool(s)); invalid -> -inf
    VPASS(S, 12)
    {
        const int R = CTY + 24, C = CTX + 24;
        for (int idx = tid; idx < R*C; idx += 512) {
            int br = 3 + idx / C, bc = 3 + idx % C;
            int o = br * BW + bc;
            HMAX(o, m)
            int gy = gy0 + br, gx = gx0 + bc;
            bool valid = gy >= hlo && gy <= hhi && gx >= 0 && gx < WW;
            MM[o] = valid ? ((S[o] == m) ? 1.0f : 0.0f) : -INFINITY;
        }
        __syncthreads();
    }

    // iteration 1
    VPASS(MM, 9)
    {
        const int R = CTY + 18, C = CTX + 18;
        for (int idx = tid; idx < R*C; idx += 512) {
            int br = 6 + idx / C, bc = 6 + idx % C;
            int o = br * BW + bc;
            HMAX(o, m)
            int gy = gy0 + br, gx = gx0 + bc;
            bool valid = gy >= hlo && gy <= hhi && gx >= 0 && gx < WW;
            SS[o] = valid ? ((m > 0.0f) ? -1.0f : S[o]) : -INFINITY;
        }
        __syncthreads();
    }
    VPASS(SS, 6)
    {
        const int R = CTY + 12, C = CTX + 12;
        for (int idx = tid; idx < R*C; idx += 512) {
            int br = 9 + idx / C, bc = 9 + idx % C;
            int o = br * BW + bc;
            HMAX(o, m)
            float ssv = SS[o];
            if (MM[o] == 0.0f && ssv >= 0.0f && ssv == m) MM[o] = 1.0f;
        }
        __syncthreads();
    }

    // iteration 2 + fused compaction
    VPASS(MM, 3)
    {
        const int R = CTY + 6, C = CTX + 6;
        for (int idx = tid; idx < R*C; idx += 512) {
            int br = 12 + idx / C, bc = 12 + idx % C;
            int o = br * BW + bc;
            HMAX(o, m)
            int gy = gy0 + br, gx = gx0 + bc;
            bool valid = gy >= hlo && gy <= hhi && gx >= 0 && gx < WW;
            SS[o] = valid ? ((m > 0.0f) ? -1.0f : S[o]) : -INFINITY;
        }
        __syncthreads();
    }
    VPASS(SS, 0)
    {
        for (int idx = tid; idx < CTY*CTX; idx += 512) {
            int br = HAL + idx / CTX, bc = HAL + idx % CTX;
            int o = br * BW + bc;
            HMAX(o, m)
            float ssv = SS[o];
            float mmv = MM[o];
            if (mmv == 0.0f && ssv >= 0.0f && ssv == m) mmv = 1.0f;
            int gy = gy0 + br, gx = gx0 + bc;
            int rem = gy * WW + gx;
            bool border = (gy >= 3) && (gy < 510) && (gx >= 3) && (gx < 510);
            float nms = (mmv > 0.0f && border) ? S[o] : 0.0f;
            if (nms > 0.0f || rem < TOPK) {
                int pos = atomicAdd(&g_count[b], 1);
                if (pos < CAP) {
                    unsigned long long key =
                        ((unsigned long long)__float_as_uint(nms) << 32) |
                        (unsigned long long)(0xFFFFFFFFu - (unsigned)rem);
                    g_cand[b * CAP + pos] = key;
                    int bin = min(NBINS-1, max(0, (int)(nms * (float)NBINS)));
                    atomicAdd(&g_hist[b * NBINS + bin], 1);
                }
            }
        }
    }
}

// per-batch: find threshold bin T (suffix >= TOPK), compact survivors, reset state
__global__ __launch_bounds__(1024) void thresh_compact_k() {
    int b = blockIdx.x;
    int t = threadIdx.x;
    __shared__ int gs[1024];
    __shared__ int sT;
    int base = NBINS - 1 - 4*t;
    int c0 = g_hist[b*NBINS + base];
    int c1 = g_hist[b*NBINS + base-1];
    int c2 = g_hist[b*NBINS + base-2];
    int c3 = g_hist[b*NBINS + base-3];
    int s = c0 + c1 + c2 + c3;
    gs[t] = s;
    // reset histogram (values already in registers)
    g_hist[b*NBINS + base]   = 0;
    g_hist[b*NBINS + base-1] = 0;
    g_hist[b*NBINS + base-2] = 0;
    g_hist[b*NBINS + base-3] = 0;
    __syncthreads();
    for (int off = 1; off < 1024; off <<= 1) {
        int v = (t >= off) ? gs[t-off] : 0;
        __syncthreads();
        gs[t] += v;
        __syncthreads();
    }
    int total = gs[1023];
    int excl = gs[t] - s;
    if (excl < TOPK && excl + s >= TOPK) {
        int T = base - 3;
        int cum = excl + c0;
        if (cum >= TOPK) T = base;
        else { cum += c1; if (cum >= TOPK) T = base-1;
               else { cum += c2; if (cum >= TOPK) T = base-2; } }
        sT = T;
    }
    if (t == 0 && total < TOPK) sT = 0;
    __syncthreads();
    int T = sT;
    int cnt = min(g_count[b], CAP);
    for (int i = t; i < cnt; i += 1024) {
        unsigned long long key = g_cand[b*CAP + i];
        float v = __uint_as_float((unsigned)(key >> 32));
        int bin = min(NBINS-1, max(0, (int)(v * (float)NBINS)));
        if (bin >= T) {
            int p = atomicAdd(&g_scount[b], 1);
            if (p < MAXS) g_surv[b*MAXS + p] = key;
        }
    }
    __syncthreads();
    if (t == 0) g_count[b] = 0;   // reset after all reads
}

// 2D-parallel partial ranking: block (jt, ib, b) accumulates tile contributions
__global__ __launch_bounds__(256) void rank_part_k() {
    int b = blockIdx.z;
    int m = min(g_scount[b], MAXS);
    const unsigned long long* sv = g_surv + b*MAXS;
    __shared__ unsigned long long sk[256];
    for (int ib = blockIdx.y; ib * 256 < m; ib += gridDim.y) {
        int i = ib * 256 + threadIdx.x;
        unsigned long long mykey = (i < m) ? sv[i] : 0ull;
        for (int jt = blockIdx.x; jt * 256 < m; jt += gridDim.x) {
            int j = jt * 256 + threadIdx.x;
            sk[threadIdx.x] = (j < m) ? sv[j] : 0ull;
            __syncthreads();
            int lim = min(256, m - jt * 256);
            int r = 0;
            if (i < m) {
                int u = 0;
                for (; u + 4 <= lim; u += 4) {
                    r += (sk[u]   > mykey) ? 1 : 0;
                    r += (sk[u+1] > mykey) ? 1 : 0;
                    r += (sk[u+2] > mykey) ? 1 : 0;
                    r += (sk[u+3] > mykey) ? 1 : 0;
                }
                for (; u < lim; ++u) r += (sk[u] > mykey) ? 1 : 0;
            }
            if (i < m && r) atomicAdd(&g_rank[b*MAXS + i], r);
            __syncthreads();
        }
    }
}

// scatter rank -> selidx slot; self-reset g_rank for next replay
__global__ __launch_bounds__(256) void scatter_k() {
    int b = blockIdx.y;
    int m = min(g_scount[b], MAXS);
    for (int i = blockIdx.x * 256 + threadIdx.x; i < m; i += gridDim.x * 256) {
        int r = g_rank[b*MAXS + i];
        g_rank[b*MAXS + i] = 0;
        if (r < TOPK) {
            unsigned long long key = g_surv[b*MAXS + i];
            int flatidx = (int)(0xFFFFFFFFu - (unsigned)(key & 0xFFFFFFFFull));
            g_selidx[b * TOPK + r] = flatidx;
        }
    }
}

__device__ __forceinline__ float bilin1(const float* base, float x, float y) {
    float x0f = floorf(x), y0f = floorf(y);
    float wx = x - x0f, wy = y - y0f;
    int x0 = min(max((int)x0f, 0), WW - 1);
    int x1 = min(max((int)x0f + 1, 0), WW - 1);
    int y0 = min(max((int)y0f, 0), HH - 1);
    int y1 = min(max((int)y0f + 1, 0), HH - 1);
    float v00 = base[y0 * WW + x0], v01 = base[y0 * WW + x1];
    float v10 = base[y1 * WW + x0], v11 = base[y1 * WW + x1];
    return v00 * (1.f - wx) * (1.f - wy) + v01 * wx * (1.f - wy)
         + v10 * (1.f - wx) * wy + v11 * wx * wy;
}

// fused: warp0 does 5x5 softmax refine; all 128 threads sample+normalize desc
__global__ __launch_bounds__(128) void refine_desc_k(const float* __restrict__ scores,
                                                     const float* __restrict__ dmap,
                                                     float* __restrict__ out) {
    int t = blockIdx.x;
    int c = threadIdx.x;
    int b = t >> 11;
    int w = c >> 5, lane = c & 31;
    __shared__ float sxy[2];

    if (t == 0 && c < BB) g_scount[c] = 0;   // reset for next replay

    if (w == 0) {
        int idx = g_selidx[t];
        int ky = idx >> 9, kx = idx & 511;
        const float* sb = scores + b * HWSZ;
        int p = lane;
        float dxf = 0.f, dyf = 0.f, v = 0.f;
        if (p < 25) {
            int dy = p / 5 - 2, dx = p % 5 - 2;
            dxf = (float)dx; dyf = (float)dy;
            int y = ky + dy, x = kx + dx;
            v = (y >= 0 && y < HH && x >= 0 && x < WW) ? sb[y * WW + x] : 0.0f;
        }
        float pv = (p < 25) ? v : -INFINITY;
#pragma unroll
        for (int o = 16; o > 0; o >>= 1) pv = fmaxf(pv, __shfl_xor_sync(0xFFFFFFFFu, pv, o));
        float e = (p < 25) ? expf((v - pv) * 10.0f) : 0.0f;
        float se = e, sxv = e * dxf, syv = e * dyf;
#pragma unroll
        for (int o = 16; o > 0; o >>= 1) {
            se  += __shfl_xor_sync(0xFFFFFFFFu, se, o);
            sxv += __shfl_xor_sync(0xFFFFFFFFu, sxv, o);
            syv += __shfl_xor_sync(0xFFFFFFFFu, syv, o);
        }
        float rx = sxv / se, ry = syv / se;
        float ddx = (dxf - rx) * 0.5f, ddy = (dyf - ry) * 0.5f;
        float dc = e * (ddx * ddx + ddy * ddy);
#pragma unroll
        for (int o = 16; o > 0; o >>= 1) dc += __shfl_xor_sync(0xFFFFFFFFu, dc, o);

        if (lane == 0) {
            float kxf = ((float)kx + rx) / 511.f * 2.f - 1.f;
            float kyf = ((float)ky + ry) / 511.f * 2.f - 1.f;
            out[KXY_OFF + t * 2 + 0] = kxf;
            out[KXY_OFF + t * 2 + 1] = kyf;
            out[DISP_OFF + t] = dc / se;
            float xs = (kxf + 1.f) * 0.5f * (WW - 1);
            float ys = (kyf + 1.f) * 0.5f * (HH - 1);
            out[SC_OFF + t] = bilin1(sb, xs, ys);
            sxy[0] = xs; sxy[1] = ys;
        }
    }
    __syncthreads();

    float x = sxy[0], y = sxy[1];
    float x0f = floorf(x), y0f = floorf(y);
    float wx = x - x0f, wy = y - y0f;
    int x0 = min(max((int)x0f, 0), WW - 1);
    int x1 = min(max((int)x0f + 1, 0), WW - 1);
    int y0 = min(max((int)y0f, 0), HH - 1);
    int y1 = min(max((int)y0f + 1, 0), HH - 1);
    const float* base = dmap + ((size_t)b * 128 + c) * HWSZ;
    float v00 = base[y0 * WW + x0], v01 = base[y0 * WW + x1];
    float v10 = base[y1 * WW + x0], v11 = base[y1 * WW + x1];
    float v = v00 * (1.f - wx) * (1.f - wy) + v01 * wx * (1.f - wy)
            + v10 * (1.f - wx) * wy + v11 * wx * wy;

    float sq = v * v;
#pragma unroll
    for (int o = 16; o > 0; o >>= 1) sq += __shfl_xor_sync(0xFFFFFFFFu, sq, o);
    __shared__ float wsum[4];
    if (lane == 0) wsum[w] = sq;
    __syncthreads();
    float tot = wsum[0] + wsum[1] + wsum[2] + wsum[3];
    float nrm = fmaxf(sqrtf(tot), 1e-12f);
    out[DESC_OFF + (size_t)t * 128 + c] = v / nrm;
}

extern "C" void kernel_launch(void* const* d_in, const int* in_sizes, int n_in,
                              void* d_out, int out_size) {
    const float* scores;
    const float* dmap;
    if (in_sizes[0] == NPIX) {
        scores = (const float*)d_in[0];
        dmap   = (const float*)d_in[1];
    } else {
        scores = (const float*)d_in[1];
        dmap   = (const float*)d_in[0];
    }
    float* out = (float*)d_out;

    static bool attr_done = false;
    if (!attr_done) {
        cudaFuncSetAttribute(nms_k, cudaFuncAttributeMaxDynamicSharedMemorySize,
                             4 * NBUF * (int)sizeof(float));
        attr_done = true;
    }

    dim3 ng(WW / CTX, HH / CTY, BB);
    nms_k<<<ng, 512, 4 * NBUF * sizeof(float)>>>(scores);

    thresh_compact_k<<<BB, 1024>>>();

    dim3 rg(8, 8, BB);
    rank_part_k<<<rg, 256>>>();

    dim3 sg(16, BB);
    scatter_k<<<sg, 256>>>();

    refine_desc_k<<<NKP, 128>>>(scores, dmap, out);
}